// round 11
// baseline (speedup 1.0000x reference)
#include <cuda_runtime.h>
#include <cuda_fp16.h>
#include <stdint.h>

#define NTOK  16384
#define DPROJ 1024
#define BM 128
#define BN 64
#define BK 32            // k halves per stage
#define HSTRIDE 40       // half row stride (20 words; conflict-free ldmatrix)
#define STAGES 3
#define MAX_MTILES 132

// A fp16 regions, indexed by flat token position t
#define A0 0UL
#define A1 (A0 + 16384UL * 1024)
#define A2 (A1 + 16384UL * 256)
#define A3 (A2 + 16384UL * 64)
#define ATOT (A3 + 16384UL * 16)
// B fp16 regions
#define B0 0UL
#define B1 (B0 + 1024UL * 1024)
#define B2 (B1 + 1024UL * 256)
#define B3 (B2 + 1024UL * 64)
#define BTOT (B3 + 1024UL * 16)

#define NB16 (BTOT / 16)
#define NA16 (NTOK * 64UL)

__device__ int g_count[4];
__device__ int g_perm[4 * NTOK];
__device__ __half g_ah[ATOT];
__device__ __half g_bh[BTOT];

__device__ __forceinline__ uint4 pack8(float4 v0, float4 v1) {
    __half2 h0 = __float22half2_rn(make_float2(v0.x, v0.y));
    __half2 h1 = __float22half2_rn(make_float2(v0.z, v0.w));
    __half2 h2 = __float22half2_rn(make_float2(v1.x, v1.y));
    __half2 h3 = __float22half2_rn(make_float2(v1.z, v1.w));
    uint4 r;
    r.x = *(uint32_t*)&h0; r.y = *(uint32_t*)&h1;
    r.z = *(uint32_t*)&h2; r.w = *(uint32_t*)&h3;
    return r;
}

__device__ __forceinline__ void conv16(const float* s, __half* d) {
    float4 v0 = *(const float4*)(s);
    float4 v1 = *(const float4*)(s + 4);
    float4 v2 = *(const float4*)(s + 8);
    float4 v3 = *(const float4*)(s + 12);
    *(uint4*)d       = pack8(v0, v1);
    *(uint4*)(d + 8) = pack8(v2, v3);
}

__global__ void k_prep(const int* __restrict__ inp,
                       const float* __restrict__ e0, const float* __restrict__ e1,
                       const float* __restrict__ e2, const float* __restrict__ e3,
                       const float* __restrict__ p0, const float* __restrict__ p1,
                       const float* __restrict__ p2, const float* __restrict__ p3)
{
    const int tid = threadIdx.x;
    const int b   = blockIdx.x;

    if (b < NTOK / 256) {
        int t = b * 256 + tid;
        int tok = inp[t];
        int c = (tok >= 200000) ? 3 : (tok >= 40000) ? 2 : (tok >= 20000) ? 1 : 0;
        unsigned m = __match_any_sync(0xffffffffu, c);
        int lane = tid & 31;
        int leader = __ffs(m) - 1;
        int base = 0;
        if (lane == leader) base = atomicAdd(&g_count[c], __popc(m));
        base = __shfl_sync(0xffffffffu, base, leader);
        int rank = __popc(m & ((1u << lane) - 1));
        g_perm[c * NTOK + base + rank] = t;
    }

    const size_t stride = (size_t)gridDim.x * blockDim.x;
    for (size_t u = (size_t)b * blockDim.x + tid; u < NB16 + NA16; u += stride) {
        if (u < NB16) {
            size_t e = u * 16;
            const float* p; size_t off;
            if (e < B1)      { p = p0; off = e - B0; }
            else if (e < B2) { p = p1; off = e - B1; }
            else if (e < B3) { p = p2; off = e - B2; }
            else             { p = p3; off = e - B3; }
            conv16(p + off, g_bh + e);
        } else {
            size_t w = u - NB16;
            int t    = (int)(w >> 6);
            int koff = (int)(w & 63) << 4;
            int tok  = inp[t];
            const float* src; int D, lo; size_t baseA;
            if      (tok < 20000)  { src = e0; D = 1024; lo = 0;      baseA = A0; }
            else if (tok < 40000)  { src = e1; D = 256;  lo = 20000;  baseA = A1; }
            else if (tok < 200000) { src = e2; D = 64;   lo = 40000;  baseA = A2; }
            else                   { src = e3; D = 16;   lo = 200000; baseA = A3; }
            if (koff < D)
                conv16(src + (size_t)(tok - lo) * D + koff,
                       g_ah + baseA + (size_t)t * D + koff);
        }
    }
}

__device__ __forceinline__ void cp16(uint32_t dst, const void* src, int valid) {
    asm volatile("cp.async.cg.shared.global [%0], [%1], 16, %2;"
                 :: "r"(dst), "l"(src), "r"(valid));
}
__device__ __forceinline__ void ldm4(uint32_t& r0, uint32_t& r1,
                                     uint32_t& r2, uint32_t& r3, uint32_t addr) {
    asm volatile("ldmatrix.sync.aligned.m8n8.x4.shared.b16 {%0,%1,%2,%3}, [%4];"
                 : "=r"(r0), "=r"(r1), "=r"(r2), "=r"(r3) : "r"(addr));
}

// Fused GEMM: block 128x64, 256 threads, 8 warps (4m x 2n), warp tile 32x32.
// 3 CTAs/SM target -> 24 warps/SM for latency hiding.
__global__ void __launch_bounds__(256, 3)
k_fused(float* __restrict__ out)
{
    extern __shared__ __half smh[];
    __half* As = smh;                                   // [STAGES][BM][HSTRIDE]
    __half* Bs = smh + STAGES * BM * HSTRIDE;           // [STAGES][BN][HSTRIDE]
    int* s_tok = (int*)(Bs + STAGES * BN * HSTRIDE);    // [BM]

    int y = blockIdx.y;
    int cluster = -1, mtile = 0, acc = 0;
#pragma unroll
    for (int c = 0; c < 4; c++) {
        int tiles = (g_count[c] + BM - 1) >> 7;
        if (cluster < 0 && y < acc + tiles) { cluster = c; mtile = y - acc; }
        acc += tiles;
    }
    if (cluster < 0) return;

    int D; size_t baseA, baseB;
    switch (cluster) {
        case 0:  D = 1024; baseA = A0; baseB = B0; break;
        case 1:  D = 256;  baseA = A1; baseB = B1; break;
        case 2:  D = 64;   baseA = A2; baseB = B2; break;
        default: D = 16;   baseA = A3; baseB = B3; break;
    }

    const int tid = threadIdx.x;
    const int cnt = g_count[cluster];

    if (tid < BM) {
        int m = mtile * BM + tid;
        s_tok[tid] = (m < cnt) ? g_perm[cluster * NTOK + m] : -1;
    }
    __syncthreads();

    // ---- loader split: tid<128 -> A (1 row, 32 halves); tid>=128 -> B (2 thr/row) ----
    const int nb = blockIdx.x * BN;
    const bool isA = (tid < BM);

    const int atok    = isA ? s_tok[tid] : -1;
    const int arow_ok = (atok >= 0);

    const int brow = (tid - BM) >> 1;            // 0..63 (B threads)
    const int blh  = ((tid - BM) & 1) * 16;      // 0 or 16

    const __half* asrc = g_ah + baseA + (size_t)(arow_ok ? atok : 0) * D;
    const __half* bsrc = g_bh + baseB + (size_t)(isA ? 0 : (nb + brow)) * D + (isA ? 0 : blh);

    const uint32_t a_smem = (uint32_t)__cvta_generic_to_shared(As) + tid * (HSTRIDE * 2);
    const uint32_t b_smem = (uint32_t)__cvta_generic_to_shared(Bs)
                            + (isA ? 0 : (brow * HSTRIDE + blh) * 2);

    const int nk = (D + BK - 1) / BK;

#define ISSUE(kbi)                                                            \
    do {                                                                      \
        int _buf = (kbi) % STAGES;                                            \
        int _kb  = (kbi) * BK;                                                \
        int _v1  = (_kb      < D) ? 16 : 0;   /* halves [0,16)  */            \
        int _v2  = (_kb + 16 < D) ? 16 : 0;   /* halves [16,32) */            \
        if (isA) {                                                            \
            int _va1 = arow_ok ? _v1 : 0;                                     \
            int _va2 = arow_ok ? _v2 : 0;                                     \
            uint32_t _ad = a_smem + _buf * (BM * HSTRIDE * 2);                \
            cp16(_ad,      asrc + _kb,      _va1);                            \
            cp16(_ad + 16, asrc + _kb + 8,  _va1);                            \
            cp16(_ad + 32, asrc + _kb + 16, _va2);                            \
            cp16(_ad + 48, asrc + _kb + 24, _va2);                            \
        } else {                                                              \
            int _vb = (blh == 0) ? _v1 : _v2;                                 \
            uint32_t _bd = b_smem + _buf * (BN * HSTRIDE * 2);                \
            cp16(_bd,      bsrc + _kb,     _vb);                              \
            cp16(_bd + 16, bsrc + _kb + 8, _vb);                              \
        }                                                                     \
    } while (0)

#pragma unroll
    for (int s = 0; s < STAGES - 1; s++) {
        if (s < nk) ISSUE(s);
        asm volatile("cp.async.commit_group;");
    }

    // ---- warp / fragment mapping: 8 warps = 4m x 2n, warp tile 32x32 ----
    const int wid  = tid >> 5, lane = tid & 31;
    const int gid  = lane >> 2, tg = lane & 3;
    const int wm   = (wid >> 1) * 32;   // 4 warps along M
    const int wn   = (wid & 1) * 32;    // 2 warps along N

    const int l8   = lane & 7;
    const int lb8  = (lane >> 3) & 1;
    const int lb16 = (lane >> 4) & 1;
    uint32_t a_off[2], b_off[2];
#pragma unroll
    for (int mi = 0; mi < 2; mi++)
        a_off[mi] = ((wm + mi * 16 + lb8 * 8 + l8) * HSTRIDE + lb16 * 8) * 2;
#pragma unroll
    for (int j = 0; j < 2; j++)
        b_off[j] = ((wn + j * 16 + lb16 * 8 + l8) * HSTRIDE + lb8 * 8) * 2;

    const uint32_t As_u = (uint32_t)__cvta_generic_to_shared(As);
    const uint32_t Bs_u = (uint32_t)__cvta_generic_to_shared(Bs);

    float accum[2][4][4];
#pragma unroll
    for (int i = 0; i < 2; i++)
#pragma unroll
        for (int j = 0; j < 4; j++)
#pragma unroll
            for (int k = 0; k < 4; k++) accum[i][j][k] = 0.f;

    for (int kbi = 0; kbi < nk; kbi++) {
        asm volatile("cp.async.wait_group 1;");
        __syncthreads();

        const uint32_t Abu = As_u + (kbi % STAGES) * (BM * HSTRIDE * 2);
        const uint32_t Bbu = Bs_u + (kbi % STAGES) * (BN * HSTRIDE * 2);

#pragma unroll
        for (int ks = 0; ks < 2; ks++) {
            const int kkb = ks * 32;   // byte offset of 16-half sub-block
            uint32_t a[2][4], b[4][2];
#pragma unroll
            for (int mi = 0; mi < 2; mi++)
                ldm4(a[mi][0], a[mi][1], a[mi][2], a[mi][3], Abu + a_off[mi] + kkb);
#pragma unroll
            for (int j = 0; j < 2; j++)
                ldm4(b[2*j][0], b[2*j][1], b[2*j+1][0], b[2*j+1][1],
                     Bbu + b_off[j] + kkb);
#pragma unroll
            for (int mi = 0; mi < 2; mi++)
#pragma unroll
                for (int ni = 0; ni < 4; ni++) {
                    asm volatile(
                        "mma.sync.aligned.m16n8k16.row.col.f32.f16.f16.f32 "
                        "{%0,%1,%2,%3}, {%4,%5,%6,%7}, {%8,%9}, {%0,%1,%2,%3};"
                        : "+f"(accum[mi][ni][0]), "+f"(accum[mi][ni][1]),
                          "+f"(accum[mi][ni][2]), "+f"(accum[mi][ni][3])
                        : "r"(a[mi][0]), "r"(a[mi][1]), "r"(a[mi][2]), "r"(a[mi][3]),
                          "r"(b[ni][0]), "r"(b[ni][1]));
                }
        }

        int pf = kbi + STAGES - 1;
        if (pf < nk) ISSUE(pf);
        asm volatile("cp.async.commit_group;");
    }
#undef ISSUE

    // ---- epilogue: scale by 32, scatter to out[token, :] ----
#pragma unroll
    for (int mi = 0; mi < 2; mi++) {
#pragma unroll
        for (int half = 0; half < 2; half++) {
            int rl = wm + mi * 16 + gid + half * 8;
            int t  = s_tok[rl];
            if (t >= 0) {
                float* op = out + (size_t)t * DPROJ + nb + wn;
#pragma unroll
                for (int ni = 0; ni < 4; ni++) {
                    float2 v;
                    v.x = accum[mi][ni][half * 2 + 0] * 32.f;
                    v.y = accum[mi][ni][half * 2 + 1] * 32.f;
                    *(float2*)(op + ni * 8 + tg * 2) = v;
                }
            }
        }
    }
}

extern "C" void kernel_launch(void* const* d_in, const int* in_sizes, int n_in,
                              void* d_out, int out_size) {
    const int*   inp   = (const int*)d_in[0];
    const float* emb0  = (const float*)d_in[1];
    const float* proj0 = (const float*)d_in[2];
    const float* emb1  = (const float*)d_in[3];
    const float* proj1 = (const float*)d_in[4];
    const float* emb2  = (const float*)d_in[5];
    const float* proj2 = (const float*)d_in[6];
    const float* emb3  = (const float*)d_in[7];
    const float* proj3 = (const float*)d_in[8];
    float* out = (float*)d_out;

    const int smem_bytes = STAGES * (BM + BN) * HSTRIDE * 2 + BM * 4;
    cudaFuncSetAttribute(k_fused, cudaFuncAttributeMaxDynamicSharedMemorySize,
                         smem_bytes);

    void* gcnt = nullptr;
    cudaGetSymbolAddress(&gcnt, g_count);
    cudaMemsetAsync(gcnt, 0, 4 * sizeof(int));

    k_prep<<<1024, 256>>>(inp, emb0, emb1, emb2, emb3,
                          proj0, proj1, proj2, proj3);

    dim3 grid(DPROJ / BN, MAX_MTILES);   // (16, 132)
    k_fused<<<grid, 256, smem_bytes>>>(out);
}

// round 14
// speedup vs baseline: 1.6852x; 1.6852x over previous
#include <cuda_runtime.h>
#include <cuda_fp16.h>
#include <stdint.h>

#define NTOK  16384
#define DPROJ 1024
#define BM 128
#define BN 128
#define BK 32            // k halves per stage
#define HSTRIDE 40       // half row stride (20 words; conflict-free ldmatrix)
#define STAGES 3
#define MAX_MTILES 262   // c0 counted twice (split-K) + others

// A fp16 regions, indexed by flat token position t
#define A0 0UL
#define A1 (A0 + 16384UL * 1024)
#define A2 (A1 + 16384UL * 256)
#define A3 (A2 + 16384UL * 64)
#define ATOT (A3 + 16384UL * 16)
// B fp16 regions
#define B0 0UL
#define B1 (B0 + 1024UL * 1024)
#define B2 (B1 + 1024UL * 256)
#define B3 (B2 + 1024UL * 64)
#define BTOT (B3 + 1024UL * 16)

#define NB16 (BTOT / 16)
#define NA16 (NTOK * 64UL)

__device__ int g_count[4];
__device__ int g_perm[4 * NTOK];
__device__ __half g_ah[ATOT];
__device__ __half g_bh[BTOT];
__device__ float g_part[(size_t)NTOK * DPROJ];   // split-K half-1 partials (c0)

__device__ __forceinline__ uint4 pack8(float4 v0, float4 v1) {
    __half2 h0 = __float22half2_rn(make_float2(v0.x, v0.y));
    __half2 h1 = __float22half2_rn(make_float2(v0.z, v0.w));
    __half2 h2 = __float22half2_rn(make_float2(v1.x, v1.y));
    __half2 h3 = __float22half2_rn(make_float2(v1.z, v1.w));
    uint4 r;
    r.x = *(uint32_t*)&h0; r.y = *(uint32_t*)&h1;
    r.z = *(uint32_t*)&h2; r.w = *(uint32_t*)&h3;
    return r;
}

__device__ __forceinline__ void conv16(const float* s, __half* d) {
    float4 v0 = *(const float4*)(s);
    float4 v1 = *(const float4*)(s + 4);
    float4 v2 = *(const float4*)(s + 8);
    float4 v3 = *(const float4*)(s + 12);
    *(uint4*)d       = pack8(v0, v1);
    *(uint4*)(d + 8) = pack8(v2, v3);
}

__global__ void k_prep(const int* __restrict__ inp,
                       const float* __restrict__ e0, const float* __restrict__ e1,
                       const float* __restrict__ e2, const float* __restrict__ e3,
                       const float* __restrict__ p0, const float* __restrict__ p1,
                       const float* __restrict__ p2, const float* __restrict__ p3)
{
    const int tid = threadIdx.x;
    const int b   = blockIdx.x;

    if (b < NTOK / 256) {
        int t = b * 256 + tid;
        int tok = inp[t];
        int c = (tok >= 200000) ? 3 : (tok >= 40000) ? 2 : (tok >= 20000) ? 1 : 0;
        unsigned m = __match_any_sync(0xffffffffu, c);
        int lane = tid & 31;
        int leader = __ffs(m) - 1;
        int base = 0;
        if (lane == leader) base = atomicAdd(&g_count[c], __popc(m));
        base = __shfl_sync(0xffffffffu, base, leader);
        int rank = __popc(m & ((1u << lane) - 1));
        g_perm[c * NTOK + base + rank] = t;
    }

    const size_t stride = (size_t)gridDim.x * blockDim.x;
    for (size_t u = (size_t)b * blockDim.x + tid; u < NB16 + NA16; u += stride) {
        if (u < NB16) {
            size_t e = u * 16;
            const float* p; size_t off;
            if (e < B1)      { p = p0; off = e - B0; }
            else if (e < B2) { p = p1; off = e - B1; }
            else if (e < B3) { p = p2; off = e - B2; }
            else             { p = p3; off = e - B3; }
            conv16(p + off, g_bh + e);
        } else {
            size_t w = u - NB16;
            int t    = (int)(w >> 6);
            int koff = (int)(w & 63) << 4;
            int tok  = inp[t];
            const float* src; int D, lo; size_t baseA;
            if      (tok < 20000)  { src = e0; D = 1024; lo = 0;      baseA = A0; }
            else if (tok < 40000)  { src = e1; D = 256;  lo = 20000;  baseA = A1; }
            else if (tok < 200000) { src = e2; D = 64;   lo = 40000;  baseA = A2; }
            else                   { src = e3; D = 16;   lo = 200000; baseA = A3; }
            if (koff < D)
                conv16(src + (size_t)(tok - lo) * D + koff,
                       g_ah + baseA + (size_t)t * D + koff);
        }
    }
}

__device__ __forceinline__ void cp16(uint32_t dst, const void* src, int valid) {
    asm volatile("cp.async.cg.shared.global [%0], [%1], 16, %2;"
                 :: "r"(dst), "l"(src), "r"(valid));
}
__device__ __forceinline__ void ldm4(uint32_t& r0, uint32_t& r1,
                                     uint32_t& r2, uint32_t& r3, uint32_t addr) {
    asm volatile("ldmatrix.sync.aligned.m8n8.x4.shared.b16 {%0,%1,%2,%3}, [%4];"
                 : "=r"(r0), "=r"(r1), "=r"(r2), "=r"(r3) : "r"(addr));
}

// Fused GEMM, split-K x2 on cluster 0. Block 128x128, 8 warps, warp tile 32x64.
__global__ void __launch_bounds__(256, 2)
k_fused(float* __restrict__ out)
{
    extern __shared__ __half smh[];
    __half* As = smh;                                   // [STAGES][BM][HSTRIDE]
    __half* Bs = smh + STAGES * BM * HSTRIDE;           // [STAGES][BN][HSTRIDE]
    int* s_tok = (int*)(Bs + STAGES * BN * HSTRIDE);    // [BM]

    // ---- map blockIdx.y -> (cluster, mtile, khalf) ----
    int y = blockIdx.y;
    int cluster = -1, mtile = 0, khalf = 0, acc = 0;
#pragma unroll
    for (int c = 0; c < 4; c++) {
        int mt = (g_count[c] + BM - 1) >> 7;
        int tiles = (c == 0) ? (mt << 1) : mt;
        if (cluster < 0 && y < acc + tiles) {
            int r = y - acc;
            cluster = c;
            if (c == 0) { mtile = r >> 1; khalf = r & 1; }
            else        { mtile = r; }
        }
        acc += tiles;
    }
    if (cluster < 0) return;

    int D; size_t baseA, baseB;
    switch (cluster) {
        case 0:  D = 1024; baseA = A0; baseB = B0; break;
        case 1:  D = 256;  baseA = A1; baseB = B1; break;
        case 2:  D = 64;   baseA = A2; baseB = B2; break;
        default: D = 16;   baseA = A3; baseB = B3; break;
    }
    const int kbase = (cluster == 0) ? khalf * 512 : 0;
    const int kend  = (cluster == 0) ? kbase + 512 : D;
    const bool partial = (cluster == 0) && (khalf == 1);

    const int tid = threadIdx.x;
    const int cnt = g_count[cluster];

    if (tid < BM) {
        int m = mtile * BM + tid;
        s_tok[tid] = (m < cnt) ? g_perm[cluster * NTOK + m] : -1;
    }
    __syncthreads();

    // ---- loader mapping: 2 threads/row, 16 halves each ----
    const int lrow = tid >> 1;
    const int lh   = (tid & 1) * 16;
    const int nb   = blockIdx.x * BN;

    const int atok = s_tok[lrow];
    const int arow_ok = (atok >= 0);
    // NOTE: + lh is load-bearing (R13 bug: dropping it duplicated the low
    // 16 halves of every k-block into the high 16 in smem).
    const __half* asrc = g_ah + baseA + (size_t)(arow_ok ? atok : 0) * D + lh;
    const __half* bsrc = g_bh + baseB + (size_t)(nb + lrow) * D + lh;

    const uint32_t a_smem = (uint32_t)__cvta_generic_to_shared(As) + (lrow * HSTRIDE + lh) * 2;
    const uint32_t b_smem = (uint32_t)__cvta_generic_to_shared(Bs) + (lrow * HSTRIDE + lh) * 2;

    const int nk = (kend - kbase + BK - 1) / BK;

#define ISSUE(kbi)                                                            \
    do {                                                                      \
        int _buf = (kbi) % STAGES;                                            \
        int _kb  = kbase + (kbi) * BK;                                        \
        int _kok = (_kb + lh < kend);                                         \
        int _va  = (_kok && arow_ok) ? 16 : 0;                                \
        int _vb  = _kok ? 16 : 0;                                             \
        const __half* _as = _kok ? asrc + _kb : asrc;                         \
        const __half* _bs = _kok ? bsrc + _kb : bsrc;                         \
        uint32_t _ad = a_smem + _buf * (BM * HSTRIDE * 2);                    \
        uint32_t _bd = b_smem + _buf * (BN * HSTRIDE * 2);                    \
        cp16(_ad,      _as,     _va);                                        \
        cp16(_ad + 16, _as + 8, _va);                                        \
        cp16(_bd,      _bs,     _vb);                                        \
        cp16(_bd + 16, _bs + 8, _vb);                                        \
    } while (0)

#pragma unroll
    for (int s = 0; s < STAGES - 1; s++) {
        if (s < nk) ISSUE(s);
        asm volatile("cp.async.commit_group;");
    }

    // ---- warp / fragment mapping: 8 warps = 4m x 2n, warp tile 32x64 ----
    const int wid  = tid >> 5, lane = tid & 31;
    const int gid  = lane >> 2, tg = lane & 3;
    const int wm   = (wid >> 1) * 32;
    const int wn   = (wid & 1) * 64;

    const int l8   = lane & 7;
    const int lb8  = (lane >> 3) & 1;
    const int lb16 = (lane >> 4) & 1;
    uint32_t a_off[2], b_off[4];
#pragma unroll
    for (int mi = 0; mi < 2; mi++)
        a_off[mi] = ((wm + mi * 16 + lb8 * 8 + l8) * HSTRIDE + lb16 * 8) * 2;
#pragma unroll
    for (int j = 0; j < 4; j++)
        b_off[j] = ((wn + j * 16 + lb16 * 8 + l8) * HSTRIDE + lb8 * 8) * 2;

    const uint32_t As_u = (uint32_t)__cvta_generic_to_shared(As);
    const uint32_t Bs_u = (uint32_t)__cvta_generic_to_shared(Bs);

    float accum[2][8][4];
#pragma unroll
    for (int i = 0; i < 2; i++)
#pragma unroll
        for (int j = 0; j < 8; j++)
#pragma unroll
            for (int k = 0; k < 4; k++) accum[i][j][k] = 0.f;

    for (int kbi = 0; kbi < nk; kbi++) {
        asm volatile("cp.async.wait_group 1;");
        __syncthreads();

        const uint32_t Abu = As_u + (kbi % STAGES) * (BM * HSTRIDE * 2);
        const uint32_t Bbu = Bs_u + (kbi % STAGES) * (BN * HSTRIDE * 2);

#pragma unroll
        for (int ks = 0; ks < 2; ks++) {
            const int kkb = ks * 32;
            uint32_t a[2][4], b[8][2];
#pragma unroll
            for (int mi = 0; mi < 2; mi++)
                ldm4(a[mi][0], a[mi][1], a[mi][2], a[mi][3], Abu + a_off[mi] + kkb);
#pragma unroll
            for (int j = 0; j < 4; j++)
                ldm4(b[2*j][0], b[2*j][1], b[2*j+1][0], b[2*j+1][1],
                     Bbu + b_off[j] + kkb);
#pragma unroll
            for (int mi = 0; mi < 2; mi++)
#pragma unroll
                for (int ni = 0; ni < 8; ni++) {
                    asm volatile(
                        "mma.sync.aligned.m16n8k16.row.col.f32.f16.f16.f32 "
                        "{%0,%1,%2,%3}, {%4,%5,%6,%7}, {%8,%9}, {%0,%1,%2,%3};"
                        : "+f"(accum[mi][ni][0]), "+f"(accum[mi][ni][1]),
                          "+f"(accum[mi][ni][2]), "+f"(accum[mi][ni][3])
                        : "r"(a[mi][0]), "r"(a[mi][1]), "r"(a[mi][2]), "r"(a[mi][3]),
                          "r"(b[ni][0]), "r"(b[ni][1]));
                }
        }

        int pf = kbi + STAGES - 1;
        if (pf < nk) ISSUE(pf);
        asm volatile("cp.async.commit_group;");
    }
#undef ISSUE

    // ---- epilogue: scale by 32; half0/others -> out, c0-half1 -> g_part ----
#pragma unroll
    for (int mi = 0; mi < 2; mi++) {
#pragma unroll
        for (int half = 0; half < 2; half++) {
            int rl = wm + mi * 16 + gid + half * 8;
            int t  = s_tok[rl];
            if (t >= 0) {
                float* op = partial
                    ? (g_part + (size_t)(mtile * BM + rl) * DPROJ + nb + wn)
                    : (out    + (size_t)t               * DPROJ + nb + wn);
#pragma unroll
                for (int ni = 0; ni < 8; ni++) {
                    float2 v;
                    v.x = accum[mi][ni][half * 2 + 0] * 32.f;
                    v.y = accum[mi][ni][half * 2 + 1] * 32.f;
                    *(float2*)(op + ni * 8 + tg * 2) = v;
                }
            }
        }
    }
}

// Fold split-K half-1 partials into out (cluster 0 rows only).
// Idempotent across graph replays: k_fused half-0 fully rewrites these out
// rows earlier in the same launch sequence.
__global__ void k_add(float* __restrict__ out)
{
    const int cnt = g_count[0];
    for (int m = blockIdx.x; m < cnt; m += gridDim.x) {
        int t = g_perm[m];   // cluster 0 region starts at offset 0
        const float4* src = (const float4*)(g_part + (size_t)m * DPROJ);
        float4* dst = (float4*)(out + (size_t)t * DPROJ);
        int c = threadIdx.x;            // 256 threads x float4 = 1024 floats
        float4 a = dst[c], b = src[c];
        a.x += b.x; a.y += b.y; a.z += b.z; a.w += b.w;
        dst[c] = a;
    }
}

extern "C" void kernel_launch(void* const* d_in, const int* in_sizes, int n_in,
                              void* d_out, int out_size) {
    const int*   inp   = (const int*)d_in[0];
    const float* emb0  = (const float*)d_in[1];
    const float* proj0 = (const float*)d_in[2];
    const float* emb1  = (const float*)d_in[3];
    const float* proj1 = (const float*)d_in[4];
    const float* emb2  = (const float*)d_in[5];
    const float* proj2 = (const float*)d_in[6];
    const float* emb3  = (const float*)d_in[7];
    const float* proj3 = (const float*)d_in[8];
    float* out = (float*)d_out;

    const int smem_bytes = STAGES * (BM + BN) * HSTRIDE * 2 + BM * 4;
    cudaFuncSetAttribute(k_fused, cudaFuncAttributeMaxDynamicSharedMemorySize,
                         smem_bytes);

    void* gcnt = nullptr;
    cudaGetSymbolAddress(&gcnt, g_count);
    cudaMemsetAsync(gcnt, 0, 4 * sizeof(int));

    k_prep<<<1024, 256>>>(inp, emb0, emb1, emb2, emb3,
                          proj0, proj1, proj2, proj3);

    dim3 grid(DPROJ / BN, MAX_MTILES);   // (8, 262)
    k_fused<<<grid, 256, smem_bytes>>>(out);
    k_add<<<1024, 256>>>(out);
}

// round 15
// speedup vs baseline: 1.9376x; 1.1498x over previous
#include <cuda_runtime.h>
#include <cuda_fp16.h>
#include <stdint.h>

#define NTOK  16384
#define DPROJ 1024
#define BM 128
#define BN 128
#define HSTRIDE 40          // half row stride (80B; 16B-aligned, conflict-free ldmatrix)
#define STAGES 4
#define MAX_MTILES 132
#define TILE_BYTES (128 * HSTRIDE * 2)   // 10240 per operand stage

// A tiles: [cluster][kb][m(16384)][40 halves], perm-compacted rows
#define AB0 0UL
#define AB1 (AB0 + 32UL * 16384 * HSTRIDE)
#define AB2 (AB1 +  8UL * 16384 * HSTRIDE)
#define AB3 (AB2 +  2UL * 16384 * HSTRIDE)
#define ATOT2 (AB3 + 1UL * 16384 * HSTRIDE)
// B tiles: [cluster][kb][n(1024)][40 halves]
#define BB0 0UL
#define BB1 (BB0 + 32UL * 1024 * HSTRIDE)
#define BB2 (BB1 +  8UL * 1024 * HSTRIDE)
#define BB3 (BB2 +  2UL * 1024 * HSTRIDE)
#define BTOT2 (BB3 + 1UL * 1024 * HSTRIDE)

#define NBU (43 * 1024)        // B conv units (32 halves each)
#define NAU (NTOK * 64UL)      // A conv unit space (16 halves each, guarded)

__device__ int g_count[4];
__device__ int g_perm[4 * NTOK];
__device__ int g_rank[NTOK];
__device__ __align__(256) __half g_ah2[ATOT2];
__device__ __align__(256) __half g_bh2[BTOT2];

__device__ __forceinline__ uint4 pack8(float4 v0, float4 v1) {
    __half2 h0 = __float22half2_rn(make_float2(v0.x, v0.y));
    __half2 h1 = __float22half2_rn(make_float2(v0.z, v0.w));
    __half2 h2 = __float22half2_rn(make_float2(v1.x, v1.y));
    __half2 h3 = __float22half2_rn(make_float2(v1.z, v1.w));
    uint4 r;
    r.x = *(uint32_t*)&h0; r.y = *(uint32_t*)&h1;
    r.z = *(uint32_t*)&h2; r.w = *(uint32_t*)&h3;
    return r;
}
__device__ __forceinline__ void conv16(const float* s, __half* d) {
    float4 v0 = *(const float4*)(s);
    float4 v1 = *(const float4*)(s + 4);
    float4 v2 = *(const float4*)(s + 8);
    float4 v3 = *(const float4*)(s + 12);
    *(uint4*)d       = pack8(v0, v1);
    *(uint4*)(d + 8) = pack8(v2, v3);
}

// ---- classify: perm + inverse perm (rank) ----
__global__ void k_classify(const int* __restrict__ inp) {
    int t = blockIdx.x * 256 + threadIdx.x;
    int tok = inp[t];
    int c = (tok >= 200000) ? 3 : (tok >= 40000) ? 2 : (tok >= 20000) ? 1 : 0;
    unsigned m = __match_any_sync(0xffffffffu, c);
    int lane = threadIdx.x & 31;
    int leader = __ffs(m) - 1;
    int base = 0;
    if (lane == leader) base = atomicAdd(&g_count[c], __popc(m));
    base = __shfl_sync(0xffffffffu, base, leader);
    int pos = base + __popc(m & ((1u << lane) - 1));
    g_perm[c * NTOK + pos] = t;
    g_rank[t] = pos;
}

// ---- convert: proj -> B tiles, gathered emb rows -> A tiles (k-blocked, padded) ----
__global__ void k_conv(const int* __restrict__ inp,
                       const float* __restrict__ e0, const float* __restrict__ e1,
                       const float* __restrict__ e2, const float* __restrict__ e3,
                       const float* __restrict__ p0, const float* __restrict__ p1,
                       const float* __restrict__ p2, const float* __restrict__ p3)
{
    const uint4 zz = make_uint4(0, 0, 0, 0);
    const size_t stride = (size_t)gridDim.x * blockDim.x;
    for (size_t u = (size_t)blockIdx.x * blockDim.x + threadIdx.x;
         u < NBU + NAU; u += stride) {
        if (u < NBU) {
            int c, kbi, n, D; const float* p; size_t bb;
            if (u < 32768)      { c = 0; kbi = u >> 10; p = p0; D = 1024; bb = BB0; }
            else if (u < 40960) { c = 1; kbi = (u - 32768) >> 10; p = p1; D = 256;  bb = BB1; }
            else if (u < 43008) { c = 2; kbi = (u - 40960) >> 10; p = p2; D = 64;   bb = BB2; }
            else                { c = 3; kbi = 0; p = p3; D = 16; bb = BB3; }
            n = (int)(u & 1023);
            const float* s = p + (size_t)n * D + kbi * 32;
            __half* d = g_bh2 + bb + ((size_t)kbi * 1024 + n) * HSTRIDE;
            conv16(s, d);
            if (D >= 32) conv16(s + 16, d + 16);
            else { *(uint4*)(d + 16) = zz; *(uint4*)(d + 24) = zz; }  // c3 pad
        } else {
            size_t w = u - NBU;
            int t    = (int)(w >> 6);
            int koff = (int)(w & 63) << 4;
            int tok  = inp[t];
            const float* src; int D, lo; size_t ab;
            if      (tok < 20000)  { src = e0; D = 1024; lo = 0;      ab = AB0; }
            else if (tok < 40000)  { src = e1; D = 256;  lo = 20000;  ab = AB1; }
            else if (tok < 200000) { src = e2; D = 64;   lo = 40000;  ab = AB2; }
            else                   { src = e3; D = 16;   lo = 200000; ab = AB3; }
            if (koff < D) {
                int m = g_rank[t];
                __half* d = g_ah2 + ab +
                    ((size_t)(koff >> 5) * 16384 + m) * HSTRIDE + (koff & 16);
                conv16(src + (size_t)(tok - lo) * D + koff, d);
                if (D == 16) { *(uint4*)(d + 16) = zz; *(uint4*)(d + 24) = zz; }
            }
        }
    }
}

__device__ __forceinline__ void ldm4(uint32_t& r0, uint32_t& r1,
                                     uint32_t& r2, uint32_t& r3, uint32_t addr) {
    asm volatile("ldmatrix.sync.aligned.m8n8.x4.shared.b16 {%0,%1,%2,%3}, [%4];"
                 : "=r"(r0), "=r"(r1), "=r"(r2), "=r"(r3) : "r"(addr));
}
__device__ __forceinline__ void bulk_cp(uint32_t dst, const void* src,
                                        uint32_t bytes, uint32_t mbar) {
    asm volatile(
        "cp.async.bulk.shared::cluster.global.mbarrier::complete_tx::bytes "
        "[%0], [%1], %2, [%3];"
        :: "r"(dst), "l"(src), "r"(bytes), "r"(mbar) : "memory");
}
__device__ __forceinline__ void mbar_wait(uint32_t addr, uint32_t parity) {
    asm volatile(
        "{\n\t.reg .pred P;\n\t"
        "W_%=:\n\t"
        "mbarrier.try_wait.parity.acquire.cta.shared::cta.b64 P, [%0], %1, 0x989680;\n\t"
        "@P bra.uni D_%=;\n\t"
        "bra.uni W_%=;\n\t"
        "D_%=:\n\t}"
        :: "r"(addr), "r"(parity) : "memory");
}

// Fused GEMM: block 128x128, 8 warps (4m x 2n), warp tile 32x64.
// Tiles arrive via cp.async.bulk (2 instr/stage) into the proven 40-half layout.
__global__ void __launch_bounds__(256, 2)
k_fused(float* __restrict__ out)
{
    extern __shared__ char smraw[];
    uint32_t sm0 = (uint32_t)__cvta_generic_to_shared(smraw);
    uint32_t ubase = (sm0 + 1023) & ~1023u;
    char* ub = smraw + (ubase - sm0);

    const uint32_t A_SM = ubase;                       // [4][10240]
    const uint32_t B_SM = ubase + STAGES * TILE_BYTES; // [4][10240]
    const uint32_t TOKO = 2 * STAGES * TILE_BYTES;     // 81920
    const uint32_t MB   = ubase + TOKO + 512;          // 4 mbarriers
    int* s_tok = (int*)(ub + TOKO);

    // ---- map blockIdx.y -> (cluster, mtile) ----
    int y = blockIdx.y;
    int cluster = -1, mtile = 0, acc = 0;
#pragma unroll
    for (int c = 0; c < 4; c++) {
        int tiles = (g_count[c] + BM - 1) >> 7;
        if (cluster < 0 && y < acc + tiles) { cluster = c; mtile = y - acc; }
        acc += tiles;
    }
    if (cluster < 0) return;

    int D; size_t abase, bbase;
    switch (cluster) {
        case 0:  D = 1024; abase = AB0; bbase = BB0; break;
        case 1:  D = 256;  abase = AB1; bbase = BB1; break;
        case 2:  D = 64;   abase = AB2; bbase = BB2; break;
        default: D = 16;   abase = AB3; bbase = BB3; break;
    }
    const int nst = (D + 31) >> 5;

    const int tid = threadIdx.x;
    const int cnt = g_count[cluster];
    const int nb  = blockIdx.x * BN;

    if (tid < BM) {
        int m = mtile * BM + tid;
        s_tok[tid] = (m < cnt) ? g_perm[cluster * NTOK + m] : -1;
    }
    if (tid == 0) {
#pragma unroll
        for (int i = 0; i < STAGES; i++)
            asm volatile("mbarrier.init.shared.b64 [%0], 1;"
                         :: "r"(MB + 8 * i) : "memory");
    }
    __syncthreads();

#define ISSUE(s_)                                                             \
    do {                                                                      \
        int _s = (s_);                                                        \
        if (tid == 0 && _s < nst) {                                           \
            uint32_t _mb = MB + 8 * (_s & 3);                                 \
            asm volatile("mbarrier.arrive.expect_tx.shared.b64 _, [%0], %1;"  \
                         :: "r"(_mb), "r"(2 * TILE_BYTES) : "memory");        \
            bulk_cp(A_SM + (_s & 3) * TILE_BYTES,                             \
                    g_ah2 + abase + ((size_t)_s * 16384 + mtile * BM) * HSTRIDE,\
                    TILE_BYTES, _mb);                                         \
            bulk_cp(B_SM + (_s & 3) * TILE_BYTES,                             \
                    g_bh2 + bbase + ((size_t)_s * 1024 + nb) * HSTRIDE,       \
                    TILE_BYTES, _mb);                                         \
        }                                                                     \
    } while (0)

    ISSUE(0); ISSUE(1); ISSUE(2);

    // ---- warp / fragment mapping: 8 warps = 4m x 2n, warp tile 32x64 ----
    const int wid  = tid >> 5, lane = tid & 31;
    const int gid  = lane >> 2, tg = lane & 3;
    const int wm   = (wid >> 1) * 32;
    const int wn   = (wid & 1) * 64;

    const int l8   = lane & 7;
    const int lb8  = (lane >> 3) & 1;
    const int lb16 = (lane >> 4) & 1;
    uint32_t a_off[2], b_off[4];
#pragma unroll
    for (int mi = 0; mi < 2; mi++)
        a_off[mi] = ((wm + mi * 16 + lb8 * 8 + l8) * HSTRIDE + lb16 * 8) * 2;
#pragma unroll
    for (int j = 0; j < 4; j++)
        b_off[j] = ((wn + j * 16 + lb16 * 8 + l8) * HSTRIDE + lb8 * 8) * 2;

    float accum[2][8][4];
#pragma unroll
    for (int i = 0; i < 2; i++)
#pragma unroll
        for (int j = 0; j < 8; j++)
#pragma unroll
            for (int k = 0; k < 4; k++) accum[i][j][k] = 0.f;

    for (int s = 0; s < nst; s++) {
        mbar_wait(MB + 8 * (s & 3), (s >> 2) & 1);

        const uint32_t Abu = A_SM + (s & 3) * TILE_BYTES;
        const uint32_t Bbu = B_SM + (s & 3) * TILE_BYTES;

#pragma unroll
        for (int ks = 0; ks < 2; ks++) {
            const int kkb = ks * 32;
            uint32_t a[2][4], b[8][2];
#pragma unroll
            for (int mi = 0; mi < 2; mi++)
                ldm4(a[mi][0], a[mi][1], a[mi][2], a[mi][3], Abu + a_off[mi] + kkb);
#pragma unroll
            for (int j = 0; j < 4; j++)
                ldm4(b[2*j][0], b[2*j][1], b[2*j+1][0], b[2*j+1][1],
                     Bbu + b_off[j] + kkb);
#pragma unroll
            for (int mi = 0; mi < 2; mi++)
#pragma unroll
                for (int ni = 0; ni < 8; ni++) {
                    asm volatile(
                        "mma.sync.aligned.m16n8k16.row.col.f32.f16.f16.f32 "
                        "{%0,%1,%2,%3}, {%4,%5,%6,%7}, {%8,%9}, {%0,%1,%2,%3};"
                        : "+f"(accum[mi][ni][0]), "+f"(accum[mi][ni][1]),
                          "+f"(accum[mi][ni][2]), "+f"(accum[mi][ni][3])
                        : "r"(a[mi][0]), "r"(a[mi][1]), "r"(a[mi][2]), "r"(a[mi][3]),
                          "r"(b[ni][0]), "r"(b[ni][1]));
                }
        }

        __syncthreads();   // all warps done reading buffer (s-1)&3 before reuse
        ISSUE(s + 3);
    }
#undef ISSUE

    // ---- epilogue: scale by 32, scatter to out[token, :] ----
#pragma unroll
    for (int mi = 0; mi < 2; mi++) {
#pragma unroll
        for (int half = 0; half < 2; half++) {
            int rl = wm + mi * 16 + gid + half * 8;
            int t  = s_tok[rl];
            if (t >= 0) {
                float* op = out + (size_t)t * DPROJ + nb + wn;
#pragma unroll
                for (int ni = 0; ni < 8; ni++) {
                    float2 v;
                    v.x = accum[mi][ni][half * 2 + 0] * 32.f;
                    v.y = accum[mi][ni][half * 2 + 1] * 32.f;
                    *(float2*)(op + ni * 8 + tg * 2) = v;
                }
            }
        }
    }
}

extern "C" void kernel_launch(void* const* d_in, const int* in_sizes, int n_in,
                              void* d_out, int out_size) {
    const int*   inp   = (const int*)d_in[0];
    const float* emb0  = (const float*)d_in[1];
    const float* proj0 = (const float*)d_in[2];
    const float* emb1  = (const float*)d_in[3];
    const float* proj1 = (const float*)d_in[4];
    const float* emb2  = (const float*)d_in[5];
    const float* proj2 = (const float*)d_in[6];
    const float* emb3  = (const float*)d_in[7];
    const float* proj3 = (const float*)d_in[8];
    float* out = (float*)d_out;

    const int smem_bytes = 2 * STAGES * TILE_BYTES + 512 + 64 + 1024;
    cudaFuncSetAttribute(k_fused, cudaFuncAttributeMaxDynamicSharedMemorySize,
                         smem_bytes);

    void* gcnt = nullptr;
    cudaGetSymbolAddress(&gcnt, g_count);
    cudaMemsetAsync(gcnt, 0, 4 * sizeof(int));

    k_classify<<<NTOK / 256, 256>>>(inp);
    k_conv<<<1024, 256>>>(inp, emb0, emb1, emb2, emb3,
                          proj0, proj1, proj2, proj3);

    dim3 grid(DPROJ / BN, MAX_MTILES);   // (8, 132)
    k_fused<<<grid, 256, smem_bytes>>>(out);
}

// round 16
// speedup vs baseline: 1.9605x; 1.0118x over previous
#include <cuda_runtime.h>
#include <cuda_fp16.h>
#include <stdint.h>

#define NTOK  16384
#define DPROJ 1024
#define BM 128
#define BN 128
#define HSTRIDE 40          // half row stride (80B; 16B-aligned, conflict-free ldmatrix)
#define STAGES 4
#define MAX_MTILES 132
#define TILE_BYTES (128 * HSTRIDE * 2)   // 10240 per operand stage

// A tiles: [cluster][kb][m(16384)][40 halves], perm-compacted rows
#define AB0 0UL
#define AB1 (AB0 + 32UL * 16384 * HSTRIDE)
#define AB2 (AB1 +  8UL * 16384 * HSTRIDE)
#define AB3 (AB2 +  2UL * 16384 * HSTRIDE)
#define ATOT2 (AB3 + 1UL * 16384 * HSTRIDE)
// B tiles: [cluster][kb][n(1024)][40 halves]
#define BB0 0UL
#define BB1 (BB0 + 32UL * 1024 * HSTRIDE)
#define BB2 (BB1 +  8UL * 1024 * HSTRIDE)
#define BB3 (BB2 +  2UL * 1024 * HSTRIDE)
#define BTOT2 (BB3 + 1UL * 1024 * HSTRIDE)

#define NBU (43 * 1024)        // B conv units (32 halves each)
#define NAU (NTOK * 64UL)      // A conv unit space (16 halves each, guarded)

__device__ int g_count[4];
__device__ int g_perm[4 * NTOK];
__device__ int g_rank[NTOK];
__device__ __align__(256) __half g_ah2[ATOT2];
__device__ __align__(256) __half g_bh2[BTOT2];

__device__ __forceinline__ uint4 pack8(float4 v0, float4 v1) {
    __half2 h0 = __float22half2_rn(make_float2(v0.x, v0.y));
    __half2 h1 = __float22half2_rn(make_float2(v0.z, v0.w));
    __half2 h2 = __float22half2_rn(make_float2(v1.x, v1.y));
    __half2 h3 = __float22half2_rn(make_float2(v1.z, v1.w));
    uint4 r;
    r.x = *(uint32_t*)&h0; r.y = *(uint32_t*)&h1;
    r.z = *(uint32_t*)&h2; r.w = *(uint32_t*)&h3;
    return r;
}
__device__ __forceinline__ void conv16(const float* s, __half* d) {
    float4 v0 = *(const float4*)(s);
    float4 v1 = *(const float4*)(s + 4);
    float4 v2 = *(const float4*)(s + 8);
    float4 v3 = *(const float4*)(s + 12);
    *(uint4*)d       = pack8(v0, v1);
    *(uint4*)(d + 8) = pack8(v2, v3);
}

// ---- classify: perm + inverse perm (rank) ----
__global__ void k_classify(const int* __restrict__ inp) {
    int t = blockIdx.x * 256 + threadIdx.x;
    int tok = inp[t];
    int c = (tok >= 200000) ? 3 : (tok >= 40000) ? 2 : (tok >= 20000) ? 1 : 0;
    unsigned m = __match_any_sync(0xffffffffu, c);
    int lane = threadIdx.x & 31;
    int leader = __ffs(m) - 1;
    int base = 0;
    if (lane == leader) base = atomicAdd(&g_count[c], __popc(m));
    base = __shfl_sync(0xffffffffu, base, leader);
    int pos = base + __popc(m & ((1u << lane) - 1));
    g_perm[c * NTOK + pos] = t;
    g_rank[t] = pos;
}

// ---- convert: proj -> B tiles, gathered emb rows -> A tiles (k-blocked, padded) ----
__global__ void k_conv(const int* __restrict__ inp,
                       const float* __restrict__ e0, const float* __restrict__ e1,
                       const float* __restrict__ e2, const float* __restrict__ e3,
                       const float* __restrict__ p0, const float* __restrict__ p1,
                       const float* __restrict__ p2, const float* __restrict__ p3)
{
    const uint4 zz = make_uint4(0, 0, 0, 0);
    const size_t stride = (size_t)gridDim.x * blockDim.x;
    for (size_t u = (size_t)blockIdx.x * blockDim.x + threadIdx.x;
         u < NBU + NAU; u += stride) {
        if (u < NBU) {
            int c, kbi, n, D; const float* p; size_t bb;
            if (u < 32768)      { c = 0; kbi = u >> 10; p = p0; D = 1024; bb = BB0; }
            else if (u < 40960) { c = 1; kbi = (u - 32768) >> 10; p = p1; D = 256;  bb = BB1; }
            else if (u < 43008) { c = 2; kbi = (u - 40960) >> 10; p = p2; D = 64;   bb = BB2; }
            else                { c = 3; kbi = 0; p = p3; D = 16; bb = BB3; }
            n = (int)(u & 1023);
            const float* s = p + (size_t)n * D + kbi * 32;
            __half* d = g_bh2 + bb + ((size_t)kbi * 1024 + n) * HSTRIDE;
            conv16(s, d);
            if (D >= 32) conv16(s + 16, d + 16);
            else { *(uint4*)(d + 16) = zz; *(uint4*)(d + 24) = zz; }  // c3 pad
        } else {
            size_t w = u - NBU;
            int t    = (int)(w >> 6);
            int koff = (int)(w & 63) << 4;
            int tok  = inp[t];
            const float* src; int D, lo; size_t ab;
            if      (tok < 20000)  { src = e0; D = 1024; lo = 0;      ab = AB0; }
            else if (tok < 40000)  { src = e1; D = 256;  lo = 20000;  ab = AB1; }
            else if (tok < 200000) { src = e2; D = 64;   lo = 40000;  ab = AB2; }
            else                   { src = e3; D = 16;   lo = 200000; ab = AB3; }
            if (koff < D) {
                int m = g_rank[t];
                __half* d = g_ah2 + ab +
                    ((size_t)(koff >> 5) * 16384 + m) * HSTRIDE + (koff & 16);
                conv16(src + (size_t)(tok - lo) * D + koff, d);
                if (D == 16) { *(uint4*)(d + 16) = zz; *(uint4*)(d + 24) = zz; }
            }
        }
    }
}

__device__ __forceinline__ void ldm4(uint32_t& r0, uint32_t& r1,
                                     uint32_t& r2, uint32_t& r3, uint32_t addr) {
    asm volatile("ldmatrix.sync.aligned.m8n8.x4.shared.b16 {%0,%1,%2,%3}, [%4];"
                 : "=r"(r0), "=r"(r1), "=r"(r2), "=r"(r3) : "r"(addr));
}
__device__ __forceinline__ void bulk_cp(uint32_t dst, const void* src,
                                        uint32_t bytes, uint32_t mbar) {
    asm volatile(
        "cp.async.bulk.shared::cluster.global.mbarrier::complete_tx::bytes "
        "[%0], [%1], %2, [%3];"
        :: "r"(dst), "l"(src), "r"(bytes), "r"(mbar) : "memory");
}
__device__ __forceinline__ void mbar_wait(uint32_t addr, uint32_t parity) {
    asm volatile(
        "{\n\t.reg .pred P;\n\t"
        "W_%=:\n\t"
        "mbarrier.try_wait.parity.acquire.cta.shared::cta.b64 P, [%0], %1, 0x989680;\n\t"
        "@P bra.uni D_%=;\n\t"
        "bra.uni W_%=;\n\t"
        "D_%=:\n\t}"
        :: "r"(addr), "r"(parity) : "memory");
}

// Fused GEMM: block 128x128, 8 warps (4m x 2n), warp tile 32x64.
// Tiles arrive via cp.async.bulk (2 instr/stage) into the proven 40-half layout.
__global__ void __launch_bounds__(256, 2)
k_fused(float* __restrict__ out)
{
    extern __shared__ char smraw[];
    uint32_t sm0 = (uint32_t)__cvta_generic_to_shared(smraw);
    uint32_t ubase = (sm0 + 1023) & ~1023u;
    char* ub = smraw + (ubase - sm0);

    const uint32_t A_SM = ubase;                       // [4][10240]
    const uint32_t B_SM = ubase + STAGES * TILE_BYTES; // [4][10240]
    const uint32_t TOKO = 2 * STAGES * TILE_BYTES;     // 81920
    const uint32_t MB   = ubase + TOKO + 512;          // 4 mbarriers
    int* s_tok = (int*)(ub + TOKO);

    // ---- map blockIdx.y -> (cluster, mtile) ----
    int y = blockIdx.y;
    int cluster = -1, mtile = 0, acc = 0;
#pragma unroll
    for (int c = 0; c < 4; c++) {
        int tiles = (g_count[c] + BM - 1) >> 7;
        if (cluster < 0 && y < acc + tiles) { cluster = c; mtile = y - acc; }
        acc += tiles;
    }
    if (cluster < 0) return;

    int D; size_t abase, bbase;
    switch (cluster) {
        case 0:  D = 1024; abase = AB0; bbase = BB0; break;
        case 1:  D = 256;  abase = AB1; bbase = BB1; break;
        case 2:  D = 64;   abase = AB2; bbase = BB2; break;
        default: D = 16;   abase = AB3; bbase = BB3; break;
    }
    const int nst = (D + 31) >> 5;

    const int tid = threadIdx.x;
    const int cnt = g_count[cluster];
    const int nb  = blockIdx.x * BN;

    if (tid < BM) {
        int m = mtile * BM + tid;
        s_tok[tid] = (m < cnt) ? g_perm[cluster * NTOK + m] : -1;
    }
    if (tid == 0) {
#pragma unroll
        for (int i = 0; i < STAGES; i++)
            asm volatile("mbarrier.init.shared.b64 [%0], 1;"
                         :: "r"(MB + 8 * i) : "memory");
    }
    __syncthreads();

#define ISSUE(s_)                                                             \
    do {                                                                      \
        int _s = (s_);                                                        \
        if (tid == 0 && _s < nst) {                                           \
            uint32_t _mb = MB + 8 * (_s & 3);                                 \
            asm volatile("mbarrier.arrive.expect_tx.shared.b64 _, [%0], %1;"  \
                         :: "r"(_mb), "r"(2 * TILE_BYTES) : "memory");        \
            bulk_cp(A_SM + (_s & 3) * TILE_BYTES,                             \
                    g_ah2 + abase + ((size_t)_s * 16384 + mtile * BM) * HSTRIDE,\
                    TILE_BYTES, _mb);                                         \
            bulk_cp(B_SM + (_s & 3) * TILE_BYTES,                             \
                    g_bh2 + bbase + ((size_t)_s * 1024 + nb) * HSTRIDE,       \
                    TILE_BYTES, _mb);                                         \
        }                                                                     \
    } while (0)

    ISSUE(0); ISSUE(1); ISSUE(2);

    // ---- warp / fragment mapping: 8 warps = 4m x 2n, warp tile 32x64 ----
    const int wid  = tid >> 5, lane = tid & 31;
    const int gid  = lane >> 2, tg = lane & 3;
    const int wm   = (wid >> 1) * 32;
    const int wn   = (wid & 1) * 64;

    const int l8   = lane & 7;
    const int lb8  = (lane >> 3) & 1;
    const int lb16 = (lane >> 4) & 1;
    uint32_t a_off[2], b_off[4];
#pragma unroll
    for (int mi = 0; mi < 2; mi++)
        a_off[mi] = ((wm + mi * 16 + lb8 * 8 + l8) * HSTRIDE + lb16 * 8) * 2;
#pragma unroll
    for (int j = 0; j < 4; j++)
        b_off[j] = ((wn + j * 16 + lb16 * 8 + l8) * HSTRIDE + lb8 * 8) * 2;

    float accum[2][8][4];
#pragma unroll
    for (int i = 0; i < 2; i++)
#pragma unroll
        for (int j = 0; j < 8; j++)
#pragma unroll
            for (int k = 0; k < 4; k++) accum[i][j][k] = 0.f;

    for (int s = 0; s < nst; s++) {
        mbar_wait(MB + 8 * (s & 3), (s >> 2) & 1);

        const uint32_t Abu = A_SM + (s & 3) * TILE_BYTES;
        const uint32_t Bbu = B_SM + (s & 3) * TILE_BYTES;

#pragma unroll
        for (int ks = 0; ks < 2; ks++) {
            const int kkb = ks * 32;
            uint32_t a[2][4], b[8][2];
#pragma unroll
            for (int mi = 0; mi < 2; mi++)
                ldm4(a[mi][0], a[mi][1], a[mi][2], a[mi][3], Abu + a_off[mi] + kkb);
#pragma unroll
            for (int j = 0; j < 4; j++)
                ldm4(b[2*j][0], b[2*j][1], b[2*j+1][0], b[2*j+1][1],
                     Bbu + b_off[j] + kkb);
#pragma unroll
            for (int mi = 0; mi < 2; mi++)
#pragma unroll
                for (int ni = 0; ni < 8; ni++) {
                    asm volatile(
                        "mma.sync.aligned.m16n8k16.row.col.f32.f16.f16.f32 "
                        "{%0,%1,%2,%3}, {%4,%5,%6,%7}, {%8,%9}, {%0,%1,%2,%3};"
                        : "+f"(accum[mi][ni][0]), "+f"(accum[mi][ni][1]),
                          "+f"(accum[mi][ni][2]), "+f"(accum[mi][ni][3])
                        : "r"(a[mi][0]), "r"(a[mi][1]), "r"(a[mi][2]), "r"(a[mi][3]),
                          "r"(b[ni][0]), "r"(b[ni][1]));
                }
        }

        __syncthreads();   // all warps done reading buffer (s-1)&3 before reuse
        ISSUE(s + 3);
    }
#undef ISSUE

    // ---- epilogue: scale by 32, scatter to out[token, :] ----
#pragma unroll
    for (int mi = 0; mi < 2; mi++) {
#pragma unroll
        for (int half = 0; half < 2; half++) {
            int rl = wm + mi * 16 + gid + half * 8;
            int t  = s_tok[rl];
            if (t >= 0) {
                float* op = out + (size_t)t * DPROJ + nb + wn;
#pragma unroll
                for (int ni = 0; ni < 8; ni++) {
                    float2 v;
                    v.x = accum[mi][ni][half * 2 + 0] * 32.f;
                    v.y = accum[mi][ni][half * 2 + 1] * 32.f;
                    *(float2*)(op + ni * 8 + tg * 2) = v;
                }
            }
        }
    }
}

extern "C" void kernel_launch(void* const* d_in, const int* in_sizes, int n_in,
                              void* d_out, int out_size) {
    const int*   inp   = (const int*)d_in[0];
    const float* emb0  = (const float*)d_in[1];
    const float* proj0 = (const float*)d_in[2];
    const float* emb1  = (const float*)d_in[3];
    const float* proj1 = (const float*)d_in[4];
    const float* emb2  = (const float*)d_in[5];
    const float* proj2 = (const float*)d_in[6];
    const float* emb3  = (const float*)d_in[7];
    const float* proj3 = (const float*)d_in[8];
    float* out = (float*)d_out;

    const int smem_bytes = 2 * STAGES * TILE_BYTES + 512 + 64 + 1024;
    cudaFuncSetAttribute(k_fused, cudaFuncAttributeMaxDynamicSharedMemorySize,
                         smem_bytes);

    void* gcnt = nullptr;
    cudaGetSymbolAddress(&gcnt, g_count);
    cudaMemsetAsync(gcnt, 0, 4 * sizeof(int));

    k_classify<<<NTOK / 256, 256>>>(inp);
    k_conv<<<1024, 256>>>(inp, emb0, emb1, emb2, emb3,
                          proj0, proj1, proj2, proj3);

    dim3 grid(DPROJ / BN, MAX_MTILES);   // (8, 132)
    k_fused<<<grid, 256, smem_bytes>>>(out);
}